// round 2
// baseline (speedup 1.0000x reference)
#include <cuda_runtime.h>

// Problem dims (fixed by the reference)
#define M_B      512
#define VF_D     4096
#define HID_D    2048
#define EMB_D    300
#define N_LABELS 2000

// Scratch for hidden layer H = relu(vfs)@W1 + b1  (512 x 2048 fp32 = 4 MB)
__device__ float g_H[M_B * HID_D];

// ---------------------------------------------------------------------------
// GEMM: C[M,N] = relu(A[M,K]) @ B[K,N] + bias[N]
// Tiles: BM=64, BN=64, BK=16. 256 threads, each computes 4x4.
// M and K are multiples of 64/16; N may be ragged (GEMM2: N=300).
// ---------------------------------------------------------------------------
#define BM 64
#define BN 64
#define BK 16

__global__ __launch_bounds__(256, 2)
void gemm_relu_bias(const float* __restrict__ A,
                    const float* __restrict__ B,
                    const float* __restrict__ bias,
                    float* __restrict__ C,
                    int M, int N, int K)
{
    __shared__ float As[BK][BM];      // transposed A tile (relu applied)
    __shared__ float Bs[BK][BN];

    const int tid = threadIdx.x;
    const int m0 = blockIdx.y * BM;
    const int n0 = blockIdx.x * BN;

    // A tile load mapping: each thread loads one float4 (relu'd) and stores transposed
    const int aRow  = tid >> 2;        // 0..63
    const int aCol4 = (tid & 3) << 2;  // 0,4,8,12
    // B tile load mapping: each thread loads one float4 row-major
    const int bRow  = tid >> 4;        // 0..15
    const int bCol4 = (tid & 15) << 2; // 0..60

    const int tRow = (tid >> 4) << 2;  // 0..60 step 4 (C row block)
    const int tCol = (tid & 15) << 2;  // 0..60 step 4 (C col block)

    float acc[4][4];
    #pragma unroll
    for (int i = 0; i < 4; i++)
        #pragma unroll
        for (int j = 0; j < 4; j++)
            acc[i][j] = 0.0f;

    const bool fullN = (n0 + BN) <= N;

    for (int k0 = 0; k0 < K; k0 += BK) {
        // --- load A tile (always full: M%64==0, K%16==0), apply relu, transpose
        {
            const float4 a = *reinterpret_cast<const float4*>(
                &A[(size_t)(m0 + aRow) * K + k0 + aCol4]);
            As[aCol4 + 0][aRow] = fmaxf(a.x, 0.0f);
            As[aCol4 + 1][aRow] = fmaxf(a.y, 0.0f);
            As[aCol4 + 2][aRow] = fmaxf(a.z, 0.0f);
            As[aCol4 + 3][aRow] = fmaxf(a.w, 0.0f);
        }
        // --- load B tile (guard ragged N)
        if (fullN) {
            *reinterpret_cast<float4*>(&Bs[bRow][bCol4]) =
                *reinterpret_cast<const float4*>(&B[(size_t)(k0 + bRow) * N + n0 + bCol4]);
        } else {
            #pragma unroll
            for (int j = 0; j < 4; j++) {
                const int col = n0 + bCol4 + j;
                Bs[bRow][bCol4 + j] = (col < N)
                    ? B[(size_t)(k0 + bRow) * N + col] : 0.0f;
            }
        }
        __syncthreads();

        #pragma unroll
        for (int k = 0; k < BK; k++) {
            const float4 ra = *reinterpret_cast<const float4*>(&As[k][tRow]);
            const float4 rb = *reinterpret_cast<const float4*>(&Bs[k][tCol]);
            const float a[4] = {ra.x, ra.y, ra.z, ra.w};
            const float b[4] = {rb.x, rb.y, rb.z, rb.w};
            #pragma unroll
            for (int i = 0; i < 4; i++)
                #pragma unroll
                for (int j = 0; j < 4; j++)
                    acc[i][j] = fmaf(a[i], b[j], acc[i][j]);
        }
        __syncthreads();
    }

    // --- epilogue: add bias, store (guard ragged N)
    #pragma unroll
    for (int i = 0; i < 4; i++) {
        const int row = m0 + tRow + i;
        #pragma unroll
        for (int j = 0; j < 4; j++) {
            const int col = n0 + tCol + j;
            if (col < N)
                C[(size_t)row * N + col] = acc[i][j] + bias[col];
        }
    }
}

// ---------------------------------------------------------------------------
// Score: out[b,n] = -sum_d relu(E[b,d] - G[n,d])^2
// Block computes a 16(b) x 16(n) tile; EMB_D=300 loaded fully into shared.
// ---------------------------------------------------------------------------
#define SD 304   // padded row stride for shared tiles

__global__ __launch_bounds__(256)
void order_score(const float* __restrict__ E,   // [512, 300]
                 const float* __restrict__ G,   // [2000, 300]
                 float* __restrict__ out)       // [512, 2000]
{
    __shared__ float Es[16][SD];
    __shared__ float Gs[16][SD];

    const int tid = threadIdx.x;
    const int n0 = blockIdx.x * 16;
    const int b0 = blockIdx.y * 16;

    // Load tiles: 16 rows x 75 float4 each = 1200 float4 per tile
    for (int idx = tid; idx < 16 * 75; idx += 256) {
        const int row = idx / 75;
        const int c4  = (idx % 75) << 2;
        *reinterpret_cast<float4*>(&Es[row][c4]) =
            *reinterpret_cast<const float4*>(&E[(size_t)(b0 + row) * EMB_D + c4]);
        *reinterpret_cast<float4*>(&Gs[row][c4]) =
            *reinterpret_cast<const float4*>(&G[(size_t)(n0 + row) * EMB_D + c4]);
    }
    __syncthreads();

    const int tb = tid >> 4;   // 0..15
    const int tn = tid & 15;   // 0..15

    float acc = 0.0f;
    #pragma unroll 5
    for (int d = 0; d < EMB_D; d += 4) {
        const float4 e = *reinterpret_cast<const float4*>(&Es[tb][d]);
        const float4 g = *reinterpret_cast<const float4*>(&Gs[tn][d]);
        float t;
        t = fmaxf(e.x - g.x, 0.0f); acc = fmaf(t, t, acc);
        t = fmaxf(e.y - g.y, 0.0f); acc = fmaf(t, t, acc);
        t = fmaxf(e.z - g.z, 0.0f); acc = fmaf(t, t, acc);
        t = fmaxf(e.w - g.w, 0.0f); acc = fmaf(t, t, acc);
    }

    out[(size_t)(b0 + tb) * N_LABELS + n0 + tn] = -acc;
}

// ---------------------------------------------------------------------------
// kernel_launch
// Inputs (metadata order): vfs[512,4096], W1[4096,2048], b1[2048],
//                          W2[2048,300], b2[300], gt_label_vecs[2000,300]
// Output: score_stack[512,2000] then vf_emb[512,300], concatenated.
// ---------------------------------------------------------------------------
extern "C" void kernel_launch(void* const* d_in, const int* in_sizes, int n_in,
                              void* d_out, int out_size)
{
    const float* vfs = (const float*)d_in[0];
    const float* W1  = (const float*)d_in[1];
    const float* b1  = (const float*)d_in[2];
    const float* W2  = (const float*)d_in[3];
    const float* b2  = (const float*)d_in[4];
    const float* G   = (const float*)d_in[5];

    float* score = (float*)d_out;                       // [512, 2000]
    float* emb   = (float*)d_out + (size_t)M_B * N_LABELS;  // [512, 300]

    float* H = nullptr;
    cudaGetSymbolAddress((void**)&H, g_H);

    // GEMM1: H = relu(vfs) @ W1 + b1   [512,2048]
    {
        dim3 grid(HID_D / BN, M_B / BM);   // (32, 8)
        gemm_relu_bias<<<grid, 256>>>(vfs, W1, b1, H, M_B, HID_D, VF_D);
    }
    // GEMM2: emb = relu(H) @ W2 + b2   [512,300]
    {
        dim3 grid((EMB_D + BN - 1) / BN, M_B / BM);  // (5, 8)
        gemm_relu_bias<<<grid, 256>>>(H, W2, b2, emb, M_B, EMB_D, HID_D);
    }
    // Score: [512, 2000]
    {
        dim3 grid(N_LABELS / 16, M_B / 16);  // (125, 32)
        order_score<<<grid, 256>>>(emb, G, score);
    }
}

// round 6
// speedup vs baseline: 3.0380x; 3.0380x over previous
#include <cuda_runtime.h>
#include <cuda_bf16.h>
#include <cstdint>

// Problem dims (fixed by the reference)
#define M_B      512
#define VF_D     4096
#define HID_D    2048
#define EMB_D    300
#define EMB_PAD  320
#define N_LABELS 2000

// ---------------------------------------------------------------------------
// Scratch (bf16 hi/lo split operands)
// ---------------------------------------------------------------------------
__device__ __nv_bfloat16 g_Ahi[M_B * VF_D];         // relu(vfs) hi
__device__ __nv_bfloat16 g_Alo[M_B * VF_D];         // relu(vfs) lo
__device__ __nv_bfloat16 g_W1hi[VF_D * HID_D];      // W1 hi [4096, 2048]
__device__ __nv_bfloat16 g_W1lo[VF_D * HID_D];
__device__ __nv_bfloat16 g_Hhi[M_B * HID_D];        // relu(H) hi
__device__ __nv_bfloat16 g_Hlo[M_B * HID_D];
__device__ __nv_bfloat16 g_W2hi[HID_D * EMB_PAD];   // W2 hi [2048, 320], cols>=300 zero
__device__ __nv_bfloat16 g_W2lo[HID_D * EMB_PAD];

// ---------------------------------------------------------------------------
// Helpers (baseline PTX only: mma.sync / ldmatrix / cp.async)
// ---------------------------------------------------------------------------
__device__ __forceinline__ uint32_t smem_to_u32(const void* p) {
    uint32_t a;
    asm("{ .reg .u64 t; cvta.to.shared.u64 t, %1; cvt.u32.u64 %0, t; }" : "=r"(a) : "l"(p));
    return a;
}

#define SWZ(off) ((off) ^ (((off) >> 3) & 0x70))

__device__ __forceinline__ void cp16(uint32_t smem, const void* g) {
    asm volatile("cp.async.cg.shared.global [%0], [%1], 16;" :: "r"(smem), "l"(g));
}
#define CP_COMMIT() asm volatile("cp.async.commit_group;" ::: "memory")
#define CP_WAIT(n)  asm volatile("cp.async.wait_group %0;" :: "n"(n) : "memory")

__device__ __forceinline__ void ldsm_x4(uint32_t* r, uint32_t addr) {
    asm volatile("ldmatrix.sync.aligned.m8n8.x4.shared.b16 {%0,%1,%2,%3}, [%4];"
        : "=r"(r[0]), "=r"(r[1]), "=r"(r[2]), "=r"(r[3]) : "r"(addr));
}
__device__ __forceinline__ void ldsm_x4_t(uint32_t* r, uint32_t addr) {
    asm volatile("ldmatrix.sync.aligned.m8n8.x4.trans.shared.b16 {%0,%1,%2,%3}, [%4];"
        : "=r"(r[0]), "=r"(r[1]), "=r"(r[2]), "=r"(r[3]) : "r"(addr));
}
__device__ __forceinline__ void mma_bf16(float* c, const uint32_t* a, const uint32_t* b) {
    asm volatile("mma.sync.aligned.m16n8k16.row.col.f32.bf16.bf16.f32 "
        "{%0,%1,%2,%3}, {%4,%5,%6,%7}, {%8,%9}, {%0,%1,%2,%3};"
        : "+f"(c[0]), "+f"(c[1]), "+f"(c[2]), "+f"(c[3])
        : "r"(a[0]), "r"(a[1]), "r"(a[2]), "r"(a[3]), "r"(b[0]), "r"(b[1]));
}

__device__ __forceinline__ void split_bf16(float r, __nv_bfloat16& hi, __nv_bfloat16& lo) {
    hi = __float2bfloat16(r);
    lo = __float2bfloat16(r - __bfloat162float(hi));
}

// ---------------------------------------------------------------------------
// Prep kernels
// ---------------------------------------------------------------------------
__global__ void relu_split_kernel(const float* __restrict__ in,
                                  __nv_bfloat16* __restrict__ hi,
                                  __nv_bfloat16* __restrict__ lo, int n4) {
    int i = blockIdx.x * blockDim.x + threadIdx.x;
    if (i >= n4) return;
    const float4 v = reinterpret_cast<const float4*>(in)[i];
    float r[4] = {fmaxf(v.x, 0.f), fmaxf(v.y, 0.f), fmaxf(v.z, 0.f), fmaxf(v.w, 0.f)};
    __nv_bfloat16 h[4], l[4];
    #pragma unroll
    for (int j = 0; j < 4; j++) split_bf16(r[j], h[j], l[j]);
    __nv_bfloat162 hp0; hp0.x = h[0]; hp0.y = h[1];
    __nv_bfloat162 hp1; hp1.x = h[2]; hp1.y = h[3];
    __nv_bfloat162 lp0; lp0.x = l[0]; lp0.y = l[1];
    __nv_bfloat162 lp1; lp1.x = l[2]; lp1.y = l[3];
    reinterpret_cast<__nv_bfloat162*>(hi)[i*2]   = hp0;
    reinterpret_cast<__nv_bfloat162*>(hi)[i*2+1] = hp1;
    reinterpret_cast<__nv_bfloat162*>(lo)[i*2]   = lp0;
    reinterpret_cast<__nv_bfloat162*>(lo)[i*2+1] = lp1;
}

// W [K, N] fp32 -> hi/lo [K, NP] bf16 (cols >= N zeroed). One row per blockIdx.y.
__global__ void split_pad_kernel(const float* __restrict__ W,
                                 __nv_bfloat16* __restrict__ Whi,
                                 __nv_bfloat16* __restrict__ Wlo,
                                 int N, int NP) {
    const int k = blockIdx.y;
    const int c = (blockIdx.x * blockDim.x + threadIdx.x) * 2;
    if (c >= NP) return;
    const float v0 = (c     < N) ? W[(size_t)k * N + c]     : 0.0f;
    const float v1 = (c + 1 < N) ? W[(size_t)k * N + c + 1] : 0.0f;
    __nv_bfloat16 h0, l0, h1, l1;
    split_bf16(v0, h0, l0); split_bf16(v1, h1, l1);
    __nv_bfloat162 hp; hp.x = h0; hp.y = h1;
    __nv_bfloat162 lp; lp.x = l0; lp.y = l1;
    *reinterpret_cast<__nv_bfloat162*>(Whi + (size_t)k * NP + c) = hp;
    *reinterpret_cast<__nv_bfloat162*>(Wlo + (size_t)k * NP + c) = lp;
}

// ---------------------------------------------------------------------------
// mma.sync GEMM: C[128,64] = A[128,K] @ B[K,64]  (bf16 hi/lo, fp32 accum)
// A k-major [M,K]; B n-major [K,ldB] loaded as [k][n] tiles (ldmatrix.trans).
// OUT_MODE 0: outHi/outLo = split(relu(C + bias))
// OUT_MODE 1: outF = C + bias (fp32), cols < Nreal
// ---------------------------------------------------------------------------
#define GM_BM 128
#define GM_BN 64
#define GM_KC 64
#define GA_B  (GM_BM * 128)            // 16 KB per A matrix
#define GB_B  (GM_BN * 128)            //  8 KB per B matrix
#define GSTG  (2 * GA_B + 2 * GB_B)    // 48 KB per stage
#define GSMEM (2 * GSTG)               // 96 KB

template<int OUT_MODE>
__global__ __launch_bounds__(256, 2)
void gemm_mma(const __nv_bfloat16* __restrict__ Ahi, const __nv_bfloat16* __restrict__ Alo,
              const __nv_bfloat16* __restrict__ Bhi, const __nv_bfloat16* __restrict__ Blo,
              const float* __restrict__ bias,
              float* __restrict__ outF,
              __nv_bfloat16* __restrict__ outHi, __nv_bfloat16* __restrict__ outLo,
              int K, int ldB, int Nreal, int ldOut)
{
    extern __shared__ char smem[];
    const uint32_t smem_base = smem_to_u32(smem);
    const int tid  = threadIdx.x;
    const int lane = tid & 31;
    const int wid  = tid >> 5;
    const int m0 = blockIdx.y * GM_BM;
    const int n0 = blockIdx.x * GM_BN;
    const int NC = K / GM_KC;

    const int wm0 = (wid >> 1) * 32;   // warp m offset within CTA tile
    const int wn0 = (wid & 1) * 32;    // warp n offset

    float acc[2][4][4];
    #pragma unroll
    for (int mi = 0; mi < 2; mi++)
        #pragma unroll
        for (int ni = 0; ni < 4; ni++)
            #pragma unroll
            for (int j = 0; j < 4; j++) acc[mi][ni][j] = 0.0f;

    // --- async stage loader: 12 x cp.async(16B) per thread -----------------
    auto load_stage = [&](int s, int k0) {
        const uint32_t base = smem_base + s * GSTG;
        #pragma unroll
        for (int t = 0; t < 4; t++) {                 // A: 1024 segs / 256 thr
            const int u = tid + t * 256;
            const int row = u >> 3, seg = u & 7;
            const uint32_t off = SWZ((uint32_t)(row * 128 + seg * 16));
            const size_t gi = (size_t)(m0 + row) * K + k0 + seg * 8;
            cp16(base + off,        Ahi + gi);
            cp16(base + GA_B + off, Alo + gi);
        }
        #pragma unroll
        for (int t = 0; t < 2; t++) {                 // B: 512 segs / 256 thr
            const int u = tid + t * 256;
            const int row = u >> 3, seg = u & 7;
            const uint32_t off = SWZ((uint32_t)(row * 128 + seg * 16));
            const size_t gi = (size_t)(k0 + row) * ldB + n0 + seg * 8;
            cp16(base + 2*GA_B + off,        Bhi + gi);
            cp16(base + 2*GA_B + GB_B + off, Blo + gi);
        }
    };

    // per-lane ldmatrix byte offsets (within a tile)
    const uint32_t aoff0 = (uint32_t)((wm0 + (lane & 15)) * 128 + (lane >> 4) * 16);
    const uint32_t boff0 = (uint32_t)((((lane >> 3) & 1) * 8 + (lane & 7)) * 128
                                      + (wn0 + (lane >> 4) * 8) * 2);

    load_stage(0, 0);
    CP_COMMIT();

    for (int c = 0; c < NC; c++) {
        if (c + 1 < NC) { load_stage((c + 1) & 1, (c + 1) * GM_KC); CP_COMMIT(); CP_WAIT(1); }
        else            { CP_WAIT(0); }
        __syncthreads();

        const uint32_t st = smem_base + (c & 1) * GSTG;
        #pragma unroll
        for (int kk = 0; kk < GM_KC; kk += 16) {
            uint32_t ah[2][4], al[2][4], bh[2][4], bl[2][4];
            #pragma unroll
            for (int mi = 0; mi < 2; mi++) {
                const uint32_t off = SWZ(aoff0 + mi * 16 * 128 + kk * 2);
                ldsm_x4(ah[mi], st + off);
                ldsm_x4(al[mi], st + GA_B + off);
            }
            #pragma unroll
            for (int p = 0; p < 2; p++) {
                const uint32_t off = SWZ(boff0 + kk * 128 + p * 32);
                ldsm_x4_t(bh[p], st + 2*GA_B + off);
                ldsm_x4_t(bl[p], st + 2*GA_B + GB_B + off);
            }
            #pragma unroll
            for (int mi = 0; mi < 2; mi++)
                #pragma unroll
                for (int ni = 0; ni < 4; ni++) {
                    const uint32_t* B1 = &bh[ni >> 1][(ni & 1) * 2];
                    const uint32_t* B2 = &bl[ni >> 1][(ni & 1) * 2];
                    mma_bf16(acc[mi][ni], ah[mi], B1);   // hi*hi
                    mma_bf16(acc[mi][ni], al[mi], B1);   // lo*hi
                    mma_bf16(acc[mi][ni], ah[mi], B2);   // hi*lo
                }
        }
        __syncthreads();
    }

    // --- epilogue ----------------------------------------------------------
    const int g = lane >> 2, t = lane & 3;
    #pragma unroll
    for (int mi = 0; mi < 2; mi++) {
        #pragma unroll
        for (int ni = 0; ni < 4; ni++) {
            const float* cc = acc[mi][ni];
            const int row0 = m0 + wm0 + mi * 16 + g;
            const int col  = n0 + wn0 + ni * 8 + t * 2;
            if (OUT_MODE == 0) {
                const float b0 = bias[col], b1 = bias[col + 1];
                #pragma unroll
                for (int h = 0; h < 2; h++) {
                    const int row = row0 + h * 8;
                    const float r0 = fmaxf(cc[h*2]   + b0, 0.f);
                    const float r1 = fmaxf(cc[h*2+1] + b1, 0.f);
                    __nv_bfloat16 h0, l0, h1, l1;
                    split_bf16(r0, h0, l0); split_bf16(r1, h1, l1);
                    __nv_bfloat162 hp; hp.x = h0; hp.y = h1;
                    __nv_bfloat162 lp; lp.x = l0; lp.y = l1;
                    *reinterpret_cast<__nv_bfloat162*>(outHi + (size_t)row * ldOut + col) = hp;
                    *reinterpret_cast<__nv_bfloat162*>(outLo + (size_t)row * ldOut + col) = lp;
                }
            } else {
                #pragma unroll
                for (int h = 0; h < 2; h++) {
                    const int row = row0 + h * 8;
                    if (col < Nreal)
                        outF[(size_t)row * ldOut + col]     = cc[h*2]   + bias[col];
                    if (col + 1 < Nreal)
                        outF[(size_t)row * ldOut + col + 1] = cc[h*2+1] + bias[col + 1];
                }
            }
        }
    }
}

// ---------------------------------------------------------------------------
// Score: out[b,n] = -sum_d relu(E[b,d] - G[n,d])^2
// 64x64 tile, 4x4 per thread, d-chunked transposed shared tiles.
// ---------------------------------------------------------------------------
#define SC_DC 75
#define SC_ST 68

__global__ __launch_bounds__(256)
void order_score(const float* __restrict__ E,   // [512, 300]
                 const float* __restrict__ G,   // [2000, 300]
                 float* __restrict__ out)       // [512, 2000]
{
    __shared__ float Es[SC_DC][SC_ST];
    __shared__ float Gs[SC_DC][SC_ST];

    const int tid = threadIdx.x;
    const int n0 = blockIdx.x * 64;
    const int b0 = blockIdx.y * 64;
    const int tb = (tid >> 4) << 2;
    const int tn = (tid & 15) << 2;

    float acc[4][4] = {};

    for (int d0 = 0; d0 < EMB_D; d0 += SC_DC) {
        __syncthreads();
        for (int i = tid; i < 64 * SC_DC; i += 256) {
            const int d = i / 64, c = i % 64;
            Es[d][c] = E[(size_t)(b0 + c) * EMB_D + d0 + d];
            const int gr = n0 + c;
            Gs[d][c] = (gr < N_LABELS) ? G[(size_t)gr * EMB_D + d0 + d] : 0.0f;
        }
        __syncthreads();
        #pragma unroll 5
        for (int d = 0; d < SC_DC; d++) {
            const float4 e = *reinterpret_cast<const float4*>(&Es[d][tb]);
            const float4 g = *reinterpret_cast<const float4*>(&Gs[d][tn]);
            const float ea[4] = {e.x, e.y, e.z, e.w};
            const float ga[4] = {g.x, g.y, g.z, g.w};
            #pragma unroll
            for (int ii = 0; ii < 4; ii++)
                #pragma unroll
                for (int jj = 0; jj < 4; jj++) {
                    const float t = fmaxf(ea[ii] - ga[jj], 0.f);
                    acc[ii][jj] = fmaf(t, t, acc[ii][jj]);
                }
        }
    }

    #pragma unroll
    for (int ii = 0; ii < 4; ii++) {
        const int b = b0 + tb + ii;
        #pragma unroll
        for (int jj = 0; jj < 4; jj++) {
            const int n = n0 + tn + jj;
            if (n < N_LABELS)
                out[(size_t)b * N_LABELS + n] = -acc[ii][jj];
        }
    }
}

// ---------------------------------------------------------------------------
// kernel_launch
// ---------------------------------------------------------------------------
extern "C" void kernel_launch(void* const* d_in, const int* in_sizes, int n_in,
                              void* d_out, int out_size)
{
    const float* vfs = (const float*)d_in[0];
    const float* W1  = (const float*)d_in[1];
    const float* b1  = (const float*)d_in[2];
    const float* W2  = (const float*)d_in[3];
    const float* b2  = (const float*)d_in[4];
    const float* G   = (const float*)d_in[5];

    float* score = (float*)d_out;                            // [512, 2000]
    float* emb   = (float*)d_out + (size_t)M_B * N_LABELS;   // [512, 300]

    __nv_bfloat16 *Ahi, *Alo, *W1hi, *W1lo, *Hhi, *Hlo, *W2hi, *W2lo;
    cudaGetSymbolAddress((void**)&Ahi,  g_Ahi);
    cudaGetSymbolAddress((void**)&Alo,  g_Alo);
    cudaGetSymbolAddress((void**)&W1hi, g_W1hi);
    cudaGetSymbolAddress((void**)&W1lo, g_W1lo);
    cudaGetSymbolAddress((void**)&Hhi,  g_Hhi);
    cudaGetSymbolAddress((void**)&Hlo,  g_Hlo);
    cudaGetSymbolAddress((void**)&W2hi, g_W2hi);
    cudaGetSymbolAddress((void**)&W2lo, g_W2lo);

    cudaFuncSetAttribute(gemm_mma<0>, cudaFuncAttributeMaxDynamicSharedMemorySize, GSMEM);
    cudaFuncSetAttribute(gemm_mma<1>, cudaFuncAttributeMaxDynamicSharedMemorySize, GSMEM);

    // Prep: relu+split vfs; split W1; split+pad W2
    relu_split_kernel<<<(M_B * VF_D / 4 + 255) / 256, 256>>>(vfs, Ahi, Alo, M_B * VF_D / 4);
    {
        dim3 g(HID_D / 512, VF_D);       // (4, 4096); 256 thr * 2 cols = 512 cols/block
        split_pad_kernel<<<g, 256>>>(W1, W1hi, W1lo, HID_D, HID_D);
    }
    {
        dim3 g(1, HID_D);                // 320 cols -> 160 threads needed; use 256
        split_pad_kernel<<<g, 256>>>(W2, W2hi, W2lo, EMB_D, EMB_PAD);
    }

    // GEMM1: H = relu(vfs) @ W1 + b1 -> relu+split -> Hhi/Hlo  [512, 2048]
    {
        dim3 g(HID_D / GM_BN, M_B / GM_BM);  // (32, 4)
        gemm_mma<0><<<g, 256, GSMEM>>>(Ahi, Alo, W1hi, W1lo, b1,
                                       nullptr, Hhi, Hlo, VF_D, HID_D, HID_D, HID_D);
    }
    // GEMM2: emb = relu(H) @ W2 + b2  (fp32)  [512, 300]
    {
        dim3 g(EMB_PAD / GM_BN, M_B / GM_BM);  // (5, 4)
        gemm_mma<1><<<g, 256, GSMEM>>>(Hhi, Hlo, W2hi, W2lo, b2,
                                       emb, nullptr, nullptr, HID_D, EMB_PAD, EMB_D, EMB_D);
    }
    // Score: [512, 2000]
    {
        dim3 g((N_LABELS + 63) / 64, M_B / 64);  // (32, 8)
        order_score<<<g, 256>>>(emb, G, score);
    }
}

// round 7
// speedup vs baseline: 3.1973x; 1.0524x over previous
#include <cuda_runtime.h>
#include <cuda_bf16.h>
#include <cstdint>

// Problem dims (fixed by the reference)
#define M_B      512
#define VF_D     4096
#define HID_D    2048
#define EMB_D    300
#define EMB_PAD  320
#define N_LABELS 2000

// ---------------------------------------------------------------------------
// Scratch (bf16 hi/lo split operands)
// ---------------------------------------------------------------------------
__device__ __nv_bfloat16 g_Ahi[M_B * VF_D];         // relu(vfs) hi
__device__ __nv_bfloat16 g_Alo[M_B * VF_D];         // relu(vfs) lo
__device__ __nv_bfloat16 g_W1hi[VF_D * HID_D];      // W1 hi [4096, 2048]
__device__ __nv_bfloat16 g_W1lo[VF_D * HID_D];
__device__ __nv_bfloat16 g_Hhi[M_B * HID_D];        // relu(H) hi
__device__ __nv_bfloat16 g_Hlo[M_B * HID_D];
__device__ __nv_bfloat16 g_W2hi[HID_D * EMB_PAD];   // W2 hi [2048, 320], cols>=300 zero
__device__ __nv_bfloat16 g_W2lo[HID_D * EMB_PAD];

// ---------------------------------------------------------------------------
// Helpers (baseline PTX only: mma.sync / ldmatrix / cp.async)
// ---------------------------------------------------------------------------
__device__ __forceinline__ uint32_t smem_to_u32(const void* p) {
    uint32_t a;
    asm("{ .reg .u64 t; cvta.to.shared.u64 t, %1; cvt.u32.u64 %0, t; }" : "=r"(a) : "l"(p));
    return a;
}

#define SWZ(off) ((off) ^ (((off) >> 3) & 0x70))

__device__ __forceinline__ void cp16(uint32_t smem, const void* g) {
    asm volatile("cp.async.cg.shared.global [%0], [%1], 16;" :: "r"(smem), "l"(g));
}
#define CP_COMMIT() asm volatile("cp.async.commit_group;" ::: "memory")
#define CP_WAIT(n)  asm volatile("cp.async.wait_group %0;" :: "n"(n) : "memory")

__device__ __forceinline__ void ldsm_x4(uint32_t* r, uint32_t addr) {
    asm volatile("ldmatrix.sync.aligned.m8n8.x4.shared.b16 {%0,%1,%2,%3}, [%4];"
        : "=r"(r[0]), "=r"(r[1]), "=r"(r[2]), "=r"(r[3]) : "r"(addr));
}
__device__ __forceinline__ void ldsm_x4_t(uint32_t* r, uint32_t addr) {
    asm volatile("ldmatrix.sync.aligned.m8n8.x4.trans.shared.b16 {%0,%1,%2,%3}, [%4];"
        : "=r"(r[0]), "=r"(r[1]), "=r"(r[2]), "=r"(r[3]) : "r"(addr));
}
__device__ __forceinline__ void mma_bf16(float* c, const uint32_t* a, const uint32_t* b) {
    asm volatile("mma.sync.aligned.m16n8k16.row.col.f32.bf16.bf16.f32 "
        "{%0,%1,%2,%3}, {%4,%5,%6,%7}, {%8,%9}, {%0,%1,%2,%3};"
        : "+f"(c[0]), "+f"(c[1]), "+f"(c[2]), "+f"(c[3])
        : "r"(a[0]), "r"(a[1]), "r"(a[2]), "r"(a[3]), "r"(b[0]), "r"(b[1]));
}

__device__ __forceinline__ void split_bf16(float r, __nv_bfloat16& hi, __nv_bfloat16& lo) {
    hi = __float2bfloat16(r);
    lo = __float2bfloat16(r - __bfloat162float(hi));
}

// ---------------------------------------------------------------------------
// Prep kernels
// ---------------------------------------------------------------------------
__global__ void relu_split_kernel(const float* __restrict__ in,
                                  __nv_bfloat16* __restrict__ hi,
                                  __nv_bfloat16* __restrict__ lo, int n4) {
    int i = blockIdx.x * blockDim.x + threadIdx.x;
    if (i >= n4) return;
    const float4 v = reinterpret_cast<const float4*>(in)[i];
    float r[4] = {fmaxf(v.x, 0.f), fmaxf(v.y, 0.f), fmaxf(v.z, 0.f), fmaxf(v.w, 0.f)};
    __nv_bfloat16 h[4], l[4];
    #pragma unroll
    for (int j = 0; j < 4; j++) split_bf16(r[j], h[j], l[j]);
    __nv_bfloat162 hp0; hp0.x = h[0]; hp0.y = h[1];
    __nv_bfloat162 hp1; hp1.x = h[2]; hp1.y = h[3];
    __nv_bfloat162 lp0; lp0.x = l[0]; lp0.y = l[1];
    __nv_bfloat162 lp1; lp1.x = l[2]; lp1.y = l[3];
    reinterpret_cast<__nv_bfloat162*>(hi)[i*2]   = hp0;
    reinterpret_cast<__nv_bfloat162*>(hi)[i*2+1] = hp1;
    reinterpret_cast<__nv_bfloat162*>(lo)[i*2]   = lp0;
    reinterpret_cast<__nv_bfloat162*>(lo)[i*2+1] = lp1;
}

// W [K, N] fp32 -> hi/lo [K, NP] bf16 (cols >= N zeroed). One row per blockIdx.y.
__global__ void split_pad_kernel(const float* __restrict__ W,
                                 __nv_bfloat16* __restrict__ Whi,
                                 __nv_bfloat16* __restrict__ Wlo,
                                 int N, int NP) {
    const int k = blockIdx.y;
    const int c = (blockIdx.x * blockDim.x + threadIdx.x) * 2;
    if (c >= NP) return;
    const float v0 = (c     < N) ? W[(size_t)k * N + c]     : 0.0f;
    const float v1 = (c + 1 < N) ? W[(size_t)k * N + c + 1] : 0.0f;
    __nv_bfloat16 h0, l0, h1, l1;
    split_bf16(v0, h0, l0); split_bf16(v1, h1, l1);
    __nv_bfloat162 hp; hp.x = h0; hp.y = h1;
    __nv_bfloat162 lp; lp.x = l0; lp.y = l1;
    *reinterpret_cast<__nv_bfloat162*>(Whi + (size_t)k * NP + c) = hp;
    *reinterpret_cast<__nv_bfloat162*>(Wlo + (size_t)k * NP + c) = lp;
}

// Seed emb with bias (split-K GEMM2 atomically accumulates on top)
__global__ void fill_bias_kernel(float* __restrict__ emb, const float* __restrict__ b2) {
    const int i = blockIdx.x * blockDim.x + threadIdx.x;
    if (i < M_B * EMB_D) emb[i] = b2[i % EMB_D];
}

// ---------------------------------------------------------------------------
// mma.sync GEMM: C[64,64] tile = A[64,K] @ B[K,64]  (bf16 hi/lo, fp32 accum)
// 8 warps, warp tile 32x16. A k-major [M,K]; B n-major [K,ldB].
// OUT_MODE 0: outHi/outLo = split(relu(C + bias))     (full K)
// OUT_MODE 2: atomicAdd(outF, C), cols < Nreal         (split-K partial)
// ---------------------------------------------------------------------------
#define GM_BM 64
#define GM_BN 64
#define GM_KC 64
#define GA_B  (GM_BM * 128)            // 8 KB per A matrix
#define GB_B  (GM_BN * 128)            // 8 KB per B matrix
#define GSTG  (2 * GA_B + 2 * GB_B)    // 32 KB per stage
#define GSMEM (2 * GSTG)               // 64 KB

template<int OUT_MODE>
__global__ __launch_bounds__(256, 2)
void gemm_mma(const __nv_bfloat16* __restrict__ Ahi, const __nv_bfloat16* __restrict__ Alo,
              const __nv_bfloat16* __restrict__ Bhi, const __nv_bfloat16* __restrict__ Blo,
              const float* __restrict__ bias,
              float* __restrict__ outF,
              __nv_bfloat16* __restrict__ outHi, __nv_bfloat16* __restrict__ outLo,
              int K, int ldB, int Nreal, int ldOut, int kLen)
{
    extern __shared__ char smem[];
    const uint32_t smem_base = smem_to_u32(smem);
    const int tid  = threadIdx.x;
    const int lane = tid & 31;
    const int wid  = tid >> 5;
    const int m0 = blockIdx.y * GM_BM;
    const int n0 = blockIdx.x * GM_BN;
    const int kOff = blockIdx.z * kLen;
    const int NC = kLen / GM_KC;

    const int wm0 = (wid >> 2) * 32;   // 2 m-groups of 32
    const int wn0 = (wid & 3) * 16;    // 4 n-groups of 16

    float acc[2][2][4];
    #pragma unroll
    for (int mi = 0; mi < 2; mi++)
        #pragma unroll
        for (int ni = 0; ni < 2; ni++)
            #pragma unroll
            for (int j = 0; j < 4; j++) acc[mi][ni][j] = 0.0f;

    // --- async stage loader: 8 x cp.async(16B) per thread ------------------
    auto load_stage = [&](int s, int k0) {
        const uint32_t base = smem_base + s * GSTG;
        #pragma unroll
        for (int t = 0; t < 2; t++) {                 // A: 512 segs / 256 thr
            const int u = tid + t * 256;
            const int row = u >> 3, seg = u & 7;
            const uint32_t off = SWZ((uint32_t)(row * 128 + seg * 16));
            const size_t gi = (size_t)(m0 + row) * K + k0 + seg * 8;
            cp16(base + off,        Ahi + gi);
            cp16(base + GA_B + off, Alo + gi);
        }
        #pragma unroll
        for (int t = 0; t < 2; t++) {                 // B: 512 segs / 256 thr
            const int u = tid + t * 256;
            const int row = u >> 3, seg = u & 7;
            const uint32_t off = SWZ((uint32_t)(row * 128 + seg * 16));
            const size_t gi = (size_t)(k0 + row) * ldB + n0 + seg * 8;
            cp16(base + 2*GA_B + off,        Bhi + gi);
            cp16(base + 2*GA_B + GB_B + off, Blo + gi);
        }
    };

    // per-lane ldmatrix byte offsets (within a tile)
    const uint32_t aoff0 = (uint32_t)((wm0 + (lane & 15)) * 128 + (lane >> 4) * 16);
    const uint32_t boff0 = (uint32_t)((((lane >> 3) & 1) * 8 + (lane & 7)) * 128
                                      + (wn0 + (lane >> 4) * 8) * 2);

    load_stage(0, kOff);
    CP_COMMIT();

    for (int c = 0; c < NC; c++) {
        if (c + 1 < NC) { load_stage((c + 1) & 1, kOff + (c + 1) * GM_KC); CP_COMMIT(); CP_WAIT(1); }
        else            { CP_WAIT(0); }
        __syncthreads();

        const uint32_t st = smem_base + (c & 1) * GSTG;
        #pragma unroll
        for (int kk = 0; kk < GM_KC; kk += 16) {
            uint32_t ah[2][4], al[2][4], bh[4], bl[4];
            #pragma unroll
            for (int mi = 0; mi < 2; mi++) {
                const uint32_t off = SWZ(aoff0 + mi * 16 * 128 + kk * 2);
                ldsm_x4(ah[mi], st + off);
                ldsm_x4(al[mi], st + GA_B + off);
            }
            {
                const uint32_t off = SWZ(boff0 + kk * 128);
                ldsm_x4_t(bh, st + 2*GA_B + off);
                ldsm_x4_t(bl, st + 2*GA_B + GB_B + off);
            }
            #pragma unroll
            for (int mi = 0; mi < 2; mi++)
                #pragma unroll
                for (int ni = 0; ni < 2; ni++) {
                    const uint32_t* B1 = &bh[ni * 2];
                    const uint32_t* B2 = &bl[ni * 2];
                    mma_bf16(acc[mi][ni], ah[mi], B1);   // hi*hi
                    mma_bf16(acc[mi][ni], al[mi], B1);   // lo*hi
                    mma_bf16(acc[mi][ni], ah[mi], B2);   // hi*lo
                }
        }
        __syncthreads();
    }

    // --- epilogue ----------------------------------------------------------
    const int g = lane >> 2, t = lane & 3;
    #pragma unroll
    for (int mi = 0; mi < 2; mi++) {
        #pragma unroll
        for (int ni = 0; ni < 2; ni++) {
            const float* cc = acc[mi][ni];
            const int row0 = m0 + wm0 + mi * 16 + g;
            const int col  = n0 + wn0 + ni * 8 + t * 2;
            if (OUT_MODE == 0) {
                const float b0 = bias[col], b1 = bias[col + 1];
                #pragma unroll
                for (int h = 0; h < 2; h++) {
                    const int row = row0 + h * 8;
                    const float r0 = fmaxf(cc[h*2]   + b0, 0.f);
                    const float r1 = fmaxf(cc[h*2+1] + b1, 0.f);
                    __nv_bfloat16 h0, l0, h1, l1;
                    split_bf16(r0, h0, l0); split_bf16(r1, h1, l1);
                    __nv_bfloat162 hp; hp.x = h0; hp.y = h1;
                    __nv_bfloat162 lp; lp.x = l0; lp.y = l1;
                    *reinterpret_cast<__nv_bfloat162*>(outHi + (size_t)row * ldOut + col) = hp;
                    *reinterpret_cast<__nv_bfloat162*>(outLo + (size_t)row * ldOut + col) = lp;
                }
            } else {
                #pragma unroll
                for (int h = 0; h < 2; h++) {
                    const int row = row0 + h * 8;
                    if (col < Nreal)
                        atomicAdd(outF + (size_t)row * ldOut + col,     cc[h*2]);
                    if (col + 1 < Nreal)
                        atomicAdd(outF + (size_t)row * ldOut + col + 1, cc[h*2+1]);
                }
            }
        }
    }
}

// ---------------------------------------------------------------------------
// Score: out[b,n] = -sum_d relu(E[b,d] - G[n,d])^2
// 64x64 tile, 4x4 per thread, d-chunked transposed shared tiles.
// ---------------------------------------------------------------------------
#define SC_DC 75
#define SC_ST 68

__global__ __launch_bounds__(256)
void order_score(const float* __restrict__ E,   // [512, 300]
                 const float* __restrict__ G,   // [2000, 300]
                 float* __restrict__ out)       // [512, 2000]
{
    __shared__ float Es[SC_DC][SC_ST];
    __shared__ float Gs[SC_DC][SC_ST];

    const int tid = threadIdx.x;
    const int n0 = blockIdx.x * 64;
    const int b0 = blockIdx.y * 64;
    const int tb = (tid >> 4) << 2;
    const int tn = (tid & 15) << 2;

    float acc[4][4] = {};

    for (int d0 = 0; d0 < EMB_D; d0 += SC_DC) {
        __syncthreads();
        for (int i = tid; i < 64 * SC_DC; i += 256) {
            const int d = i / 64, c = i % 64;
            Es[d][c] = E[(size_t)(b0 + c) * EMB_D + d0 + d];
            const int gr = n0 + c;
            Gs[d][c] = (gr < N_LABELS) ? G[(size_t)gr * EMB_D + d0 + d] : 0.0f;
        }
        __syncthreads();
        #pragma unroll 5
        for (int d = 0; d < SC_DC; d++) {
            const float4 e = *reinterpret_cast<const float4*>(&Es[d][tb]);
            const float4 g = *reinterpret_cast<const float4*>(&Gs[d][tn]);
            const float ea[4] = {e.x, e.y, e.z, e.w};
            const float ga[4] = {g.x, g.y, g.z, g.w};
            #pragma unroll
            for (int ii = 0; ii < 4; ii++)
                #pragma unroll
                for (int jj = 0; jj < 4; jj++) {
                    const float t = fmaxf(ea[ii] - ga[jj], 0.f);
                    acc[ii][jj] = fmaf(t, t, acc[ii][jj]);
                }
        }
    }

    #pragma unroll
    for (int ii = 0; ii < 4; ii++) {
        const int b = b0 + tb + ii;
        #pragma unroll
        for (int jj = 0; jj < 4; jj++) {
            const int n = n0 + tn + jj;
            if (n < N_LABELS)
                out[(size_t)b * N_LABELS + n] = -acc[ii][jj];
        }
    }
}

// ---------------------------------------------------------------------------
// kernel_launch
// ---------------------------------------------------------------------------
extern "C" void kernel_launch(void* const* d_in, const int* in_sizes, int n_in,
                              void* d_out, int out_size)
{
    const float* vfs = (const float*)d_in[0];
    const float* W1  = (const float*)d_in[1];
    const float* b1  = (const float*)d_in[2];
    const float* W2  = (const float*)d_in[3];
    const float* b2  = (const float*)d_in[4];
    const float* G   = (const float*)d_in[5];

    float* score = (float*)d_out;                            // [512, 2000]
    float* emb   = (float*)d_out + (size_t)M_B * N_LABELS;   // [512, 300]

    __nv_bfloat16 *Ahi, *Alo, *W1hi, *W1lo, *Hhi, *Hlo, *W2hi, *W2lo;
    cudaGetSymbolAddress((void**)&Ahi,  g_Ahi);
    cudaGetSymbolAddress((void**)&Alo,  g_Alo);
    cudaGetSymbolAddress((void**)&W1hi, g_W1hi);
    cudaGetSymbolAddress((void**)&W1lo, g_W1lo);
    cudaGetSymbolAddress((void**)&Hhi,  g_Hhi);
    cudaGetSymbolAddress((void**)&Hlo,  g_Hlo);
    cudaGetSymbolAddress((void**)&W2hi, g_W2hi);
    cudaGetSymbolAddress((void**)&W2lo, g_W2lo);

    cudaFuncSetAttribute(gemm_mma<0>, cudaFuncAttributeMaxDynamicSharedMemorySize, GSMEM);
    cudaFuncSetAttribute(gemm_mma<2>, cudaFuncAttributeMaxDynamicSharedMemorySize, GSMEM);

    // Prep: relu+split vfs; split W1; split+pad W2; seed emb with bias
    relu_split_kernel<<<(M_B * VF_D / 4 + 255) / 256, 256>>>(vfs, Ahi, Alo, M_B * VF_D / 4);
    {
        dim3 g(HID_D / 512, VF_D);
        split_pad_kernel<<<g, 256>>>(W1, W1hi, W1lo, HID_D, HID_D);
    }
    {
        dim3 g(1, HID_D);
        split_pad_kernel<<<g, 256>>>(W2, W2hi, W2lo, EMB_D, EMB_PAD);
    }
    fill_bias_kernel<<<(M_B * EMB_D + 255) / 256, 256>>>(emb, b2);

    // GEMM1: H = relu(vfs) @ W1 + b1 -> relu+split -> Hhi/Hlo  [512, 2048]
    {
        dim3 g(HID_D / GM_BN, M_B / GM_BM, 1);  // (32, 8, 1) = 256 CTAs
        gemm_mma<0><<<g, 256, GSMEM>>>(Ahi, Alo, W1hi, W1lo, b1,
                                       nullptr, Hhi, Hlo, VF_D, HID_D, HID_D, HID_D, VF_D);
    }
    // GEMM2 (split-K x4): emb += relu(H) @ W2  (fp32 atomics; bias pre-seeded)
    {
        dim3 g(EMB_PAD / GM_BN, M_B / GM_BM, 4);  // (5, 8, 4) = 160 CTAs
        gemm_mma<2><<<g, 256, GSMEM>>>(Hhi, Hlo, W2hi, W2lo, nullptr,
                                       emb, nullptr, nullptr, HID_D, EMB_PAD, EMB_D, EMB_D,
                                       HID_D / 4);
    }
    // Score: [512, 2000]
    {
        dim3 g((N_LABELS + 63) / 64, M_B / 64);  // (32, 8)
        order_score<<<g, 256>>>(emb, G, score);
    }
}

// round 10
// speedup vs baseline: 3.2941x; 1.0303x over previous
#include <cuda_runtime.h>
#include <cuda_bf16.h>
#include <cstdint>

// Problem dims (fixed by the reference)
#define M_B      512
#define VF_D     4096
#define HID_D    2048
#define EMB_D    300
#define EMB_PAD  320
#define N_LABELS 2000

// ---------------------------------------------------------------------------
// Scratch (bf16 hi/lo split operands)
// ---------------------------------------------------------------------------
__device__ __nv_bfloat16 g_Ahi[M_B * VF_D];
__device__ __nv_bfloat16 g_Alo[M_B * VF_D];
__device__ __nv_bfloat16 g_W1hi[VF_D * HID_D];
__device__ __nv_bfloat16 g_W1lo[VF_D * HID_D];
__device__ __nv_bfloat16 g_Hhi[M_B * HID_D];
__device__ __nv_bfloat16 g_Hlo[M_B * HID_D];
__device__ __nv_bfloat16 g_W2hi[HID_D * EMB_PAD];
__device__ __nv_bfloat16 g_W2lo[HID_D * EMB_PAD];

// ---------------------------------------------------------------------------
// Helpers (baseline PTX only: mma.sync / ldmatrix / cp.async / f32x2)
// ---------------------------------------------------------------------------
#define SWZ(off) ((off) ^ (((off) >> 3) & 0x70))

__device__ __forceinline__ uint32_t smem_u32(const void* p) {
    uint32_t a;
    asm("{ .reg .u64 t; cvta.to.shared.u64 t, %1; cvt.u32.u64 %0, t; }" : "=r"(a) : "l"(p));
    return a;
}

__device__ __forceinline__ void cp16(uint32_t smem, const void* g) {
    asm volatile("cp.async.cg.shared.global [%0], [%1], 16;" :: "r"(smem), "l"(g));
}
#define CP_COMMIT() asm volatile("cp.async.commit_group;" ::: "memory")
#define CP_WAIT(n)  asm volatile("cp.async.wait_group %0;" :: "n"(n) : "memory")

__device__ __forceinline__ void ldsm_x4(uint32_t* r, uint32_t addr) {
    asm volatile("ldmatrix.sync.aligned.m8n8.x4.shared.b16 {%0,%1,%2,%3}, [%4];"
        : "=r"(r[0]), "=r"(r[1]), "=r"(r[2]), "=r"(r[3]) : "r"(addr));
}
__device__ __forceinline__ void ldsm_x4_t(uint32_t* r, uint32_t addr) {
    asm volatile("ldmatrix.sync.aligned.m8n8.x4.trans.shared.b16 {%0,%1,%2,%3}, [%4];"
        : "=r"(r[0]), "=r"(r[1]), "=r"(r[2]), "=r"(r[3]) : "r"(addr));
}
__device__ __forceinline__ void mma_bf16(float* c, const uint32_t* a, const uint32_t* b) {
    asm volatile("mma.sync.aligned.m16n8k16.row.col.f32.bf16.bf16.f32 "
        "{%0,%1,%2,%3}, {%4,%5,%6,%7}, {%8,%9}, {%0,%1,%2,%3};"
        : "+f"(c[0]), "+f"(c[1]), "+f"(c[2]), "+f"(c[3])
        : "r"(a[0]), "r"(a[1]), "r"(a[2]), "r"(a[3]), "r"(b[0]), "r"(b[1]));
}

__device__ __forceinline__ void split_bf16(float r, __nv_bfloat16& hi, __nv_bfloat16& lo) {
    hi = __float2bfloat16(r);
    lo = __float2bfloat16(r - __bfloat162float(hi));
}

// ---------------------------------------------------------------------------
// Prep kernels
// ---------------------------------------------------------------------------
__global__ void relu_split_kernel(const float* __restrict__ in,
                                  __nv_bfloat16* __restrict__ hi,
                                  __nv_bfloat16* __restrict__ lo, int n4) {
    int i = blockIdx.x * blockDim.x + threadIdx.x;
    if (i >= n4) return;
    const float4 v = reinterpret_cast<const float4*>(in)[i];
    float r[4] = {fmaxf(v.x, 0.f), fmaxf(v.y, 0.f), fmaxf(v.z, 0.f), fmaxf(v.w, 0.f)};
    __nv_bfloat16 h[4], l[4];
    #pragma unroll
    for (int j = 0; j < 4; j++) split_bf16(r[j], h[j], l[j]);
    __nv_bfloat162 hp0; hp0.x = h[0]; hp0.y = h[1];
    __nv_bfloat162 hp1; hp1.x = h[2]; hp1.y = h[3];
    __nv_bfloat162 lp0; lp0.x = l[0]; lp0.y = l[1];
    __nv_bfloat162 lp1; lp1.x = l[2]; lp1.y = l[3];
    reinterpret_cast<__nv_bfloat162*>(hi)[i*2]   = hp0;
    reinterpret_cast<__nv_bfloat162*>(hi)[i*2+1] = hp1;
    reinterpret_cast<__nv_bfloat162*>(lo)[i*2]   = lp0;
    reinterpret_cast<__nv_bfloat162*>(lo)[i*2+1] = lp1;
}

// W [K, N] fp32 -> hi/lo [K, NP] bf16 (cols >= N zeroed). One row per blockIdx.y.
__global__ void split_pad_kernel(const float* __restrict__ W,
                                 __nv_bfloat16* __restrict__ Whi,
                                 __nv_bfloat16* __restrict__ Wlo,
                                 int N, int NP) {
    const int k = blockIdx.y;
    const int c = (blockIdx.x * blockDim.x + threadIdx.x) * 2;
    if (c >= NP) return;
    const float v0 = (c     < N) ? W[(size_t)k * N + c]     : 0.0f;
    const float v1 = (c + 1 < N) ? W[(size_t)k * N + c + 1] : 0.0f;
    __nv_bfloat16 h0, l0, h1, l1;
    split_bf16(v0, h0, l0); split_bf16(v1, h1, l1);
    __nv_bfloat162 hp; hp.x = h0; hp.y = h1;
    __nv_bfloat162 lp; lp.x = l0; lp.y = l1;
    *reinterpret_cast<__nv_bfloat162*>(Whi + (size_t)k * NP + c) = hp;
    *reinterpret_cast<__nv_bfloat162*>(Wlo + (size_t)k * NP + c) = lp;
}

// Seed emb with bias via float4 (EMB_D = 300 = 75 float4 per row)
__global__ void fill_bias_kernel(float4* __restrict__ emb4, const float4* __restrict__ b2_4) {
    const int i = blockIdx.x * blockDim.x + threadIdx.x;
    if (i < M_B * (EMB_D / 4)) emb4[i] = b2_4[i % (EMB_D / 4)];
}

// ---------------------------------------------------------------------------
// mma.sync GEMM: C[64,64] tile = A[64,K] @ B[K,64]  (bf16 hi/lo, fp32 accum)
// 3-stage cp.async pipeline, ONE __syncthreads per k-chunk.
// OUT_MODE 0: outHi/outLo = split(relu(C + bias))     (full K)
// OUT_MODE 2: atomicAdd(outF, C), cols < Nreal         (split-K partial)
// ---------------------------------------------------------------------------
#define GM_BM 64
#define GM_BN 64
#define GM_KC 64
#define GA_B  (GM_BM * 128)            // 8 KB per A matrix
#define GB_B  (GM_BN * 128)            // 8 KB per B matrix
#define GSTG  (2 * GA_B + 2 * GB_B)    // 32 KB per stage
#define GSMEM (3 * GSTG)               // 96 KB (3 stages)

template<int OUT_MODE>
__global__ __launch_bounds__(256, 2)
void gemm_mma(const __nv_bfloat16* __restrict__ Ahi, const __nv_bfloat16* __restrict__ Alo,
              const __nv_bfloat16* __restrict__ Bhi, const __nv_bfloat16* __restrict__ Blo,
              const float* __restrict__ bias,
              float* __restrict__ outF,
              __nv_bfloat16* __restrict__ outHi, __nv_bfloat16* __restrict__ outLo,
              int K, int ldB, int Nreal, int ldOut, int kLen)
{
    extern __shared__ char smem[];
    const uint32_t smem_base = smem_u32(smem);
    const int tid  = threadIdx.x;
    const int lane = tid & 31;
    const int wid  = tid >> 5;
    const int m0 = blockIdx.y * GM_BM;
    const int n0 = blockIdx.x * GM_BN;
    const int kOff = blockIdx.z * kLen;
    const int NC = kLen / GM_KC;          // >= 8 for all uses

    const int wm0 = (wid >> 2) * 32;
    const int wn0 = (wid & 3) * 16;

    float acc[2][2][4];
    #pragma unroll
    for (int mi = 0; mi < 2; mi++)
        #pragma unroll
        for (int ni = 0; ni < 2; ni++)
            #pragma unroll
            for (int j = 0; j < 4; j++) acc[mi][ni][j] = 0.0f;

    auto load_stage = [&](int s, int k0) {
        const uint32_t base = smem_base + s * GSTG;
        #pragma unroll
        for (int t = 0; t < 2; t++) {
            const int u = tid + t * 256;
            const int row = u >> 3, seg = u & 7;
            const uint32_t off = SWZ((uint32_t)(row * 128 + seg * 16));
            const size_t gi = (size_t)(m0 + row) * K + k0 + seg * 8;
            cp16(base + off,        Ahi + gi);
            cp16(base + GA_B + off, Alo + gi);
        }
        #pragma unroll
        for (int t = 0; t < 2; t++) {
            const int u = tid + t * 256;
            const int row = u >> 3, seg = u & 7;
            const uint32_t off = SWZ((uint32_t)(row * 128 + seg * 16));
            const size_t gi = (size_t)(k0 + row) * ldB + n0 + seg * 8;
            cp16(base + 2*GA_B + off,        Bhi + gi);
            cp16(base + 2*GA_B + GB_B + off, Blo + gi);
        }
    };

    const uint32_t aoff0 = (uint32_t)((wm0 + (lane & 15)) * 128 + (lane >> 4) * 16);
    const uint32_t boff0 = (uint32_t)((((lane >> 3) & 1) * 8 + (lane & 7)) * 128
                                      + (wn0 + (lane >> 4) * 8) * 2);

    // prologue: 2 stages in flight
    load_stage(0, kOff);           CP_COMMIT();
    load_stage(1, kOff + GM_KC);   CP_COMMIT();

    for (int c = 0; c < NC; c++) {
        if (c < NC - 1) { CP_WAIT(1); }   // stage c complete (1 group may stay pending)
        else            { CP_WAIT(0); }
        __syncthreads();                   // all warps see stage c; old slot free for c+2
        if (c + 2 < NC) { load_stage((c + 2) % 3, kOff + (c + 2) * GM_KC); CP_COMMIT(); }

        const uint32_t st = smem_base + (c % 3) * GSTG;
        #pragma unroll
        for (int kk = 0; kk < GM_KC; kk += 16) {
            uint32_t ah[2][4], al[2][4], bh[4], bl[4];
            #pragma unroll
            for (int mi = 0; mi < 2; mi++) {
                const uint32_t off = SWZ(aoff0 + mi * 16 * 128 + kk * 2);
                ldsm_x4(ah[mi], st + off);
                ldsm_x4(al[mi], st + GA_B + off);
            }
            {
                const uint32_t off = SWZ(boff0 + kk * 128);
                ldsm_x4_t(bh, st + 2*GA_B + off);
                ldsm_x4_t(bl, st + 2*GA_B + GB_B + off);
            }
            #pragma unroll
            for (int mi = 0; mi < 2; mi++)
                #pragma unroll
                for (int ni = 0; ni < 2; ni++) {
                    const uint32_t* B1 = &bh[ni * 2];
                    const uint32_t* B2 = &bl[ni * 2];
                    mma_bf16(acc[mi][ni], ah[mi], B1);   // hi*hi
                    mma_bf16(acc[mi][ni], al[mi], B1);   // lo*hi
                    mma_bf16(acc[mi][ni], ah[mi], B2);   // hi*lo
                }
        }
    }

    // --- epilogue ----------------------------------------------------------
    const int g = lane >> 2, t = lane & 3;
    #pragma unroll
    for (int mi = 0; mi < 2; mi++) {
        #pragma unroll
        for (int ni = 0; ni < 2; ni++) {
            const float* cc = acc[mi][ni];
            const int row0 = m0 + wm0 + mi * 16 + g;
            const int col  = n0 + wn0 + ni * 8 + t * 2;
            if (OUT_MODE == 0) {
                const float b0 = bias[col], b1 = bias[col + 1];
                #pragma unroll
                for (int h = 0; h < 2; h++) {
                    const int row = row0 + h * 8;
                    const float r0 = fmaxf(cc[h*2]   + b0, 0.f);
                    const float r1 = fmaxf(cc[h*2+1] + b1, 0.f);
                    __nv_bfloat16 h0, l0, h1, l1;
                    split_bf16(r0, h0, l0); split_bf16(r1, h1, l1);
                    __nv_bfloat162 hp; hp.x = h0; hp.y = h1;
                    __nv_bfloat162 lp; lp.x = l0; lp.y = l1;
                    *reinterpret_cast<__nv_bfloat162*>(outHi + (size_t)row * ldOut + col) = hp;
                    *reinterpret_cast<__nv_bfloat162*>(outLo + (size_t)row * ldOut + col) = lp;
                }
            } else {
                #pragma unroll
                for (int h = 0; h < 2; h++) {
                    const int row = row0 + h * 8;
                    if (col < Nreal)
                        atomicAdd(outF + (size_t)row * ldOut + col,     cc[h*2]);
                    if (col + 1 < Nreal)
                        atomicAdd(outF + (size_t)row * ldOut + col + 1, cc[h*2+1]);
                }
            }
        }
    }
}

// ---------------------------------------------------------------------------
// Score: out[b,n] = -sum_d relu(E[b,d] - G[n,d])^2
// 64x64 tile, 4x4 per thread. d-pairs accumulated with packed fma.rn.f32x2
// (FFMA2): acc2 += relu(t)^2 per half. d-chunk = 60 (even, 300 = 5*60).
// ---------------------------------------------------------------------------
#define SC_DC 60
#define SC_ST 68

__global__ __launch_bounds__(256)
void order_score(const float* __restrict__ E,   // [512, 300]
                 const float* __restrict__ G,   // [2000, 300]
                 float* __restrict__ out)       // [512, 2000]
{
    __shared__ float Es[SC_DC][SC_ST];
    __shared__ float Gs[SC_DC][SC_ST];

    const int tid = threadIdx.x;
    const int n0 = blockIdx.x * 64;
    const int b0 = blockIdx.y * 64;
    const int tb = (tid >> 4) << 2;
    const int tn = (tid & 15) << 2;

    unsigned long long acc2[4][4];
    #pragma unroll
    for (int ii = 0; ii < 4; ii++)
        #pragma unroll
        for (int jj = 0; jj < 4; jj++) acc2[ii][jj] = 0ull;

    for (int d0 = 0; d0 < EMB_D; d0 += SC_DC) {
        __syncthreads();
        for (int i = tid; i < 64 * SC_DC; i += 256) {
            const int d = i / 64, c = i % 64;
            Es[d][c] = E[(size_t)(b0 + c) * EMB_D + d0 + d];
            const int gr = n0 + c;
            Gs[d][c] = (gr < N_LABELS) ? G[(size_t)gr * EMB_D + d0 + d] : 0.0f;
        }
        __syncthreads();
        #pragma unroll 6
        for (int d = 0; d < SC_DC; d += 2) {
            const float4 e0 = *reinterpret_cast<const float4*>(&Es[d][tb]);
            const float4 e1 = *reinterpret_cast<const float4*>(&Es[d+1][tb]);
            const float4 g0 = *reinterpret_cast<const float4*>(&Gs[d][tn]);
            const float4 g1 = *reinterpret_cast<const float4*>(&Gs[d+1][tn]);
            const float ea0[4] = {e0.x, e0.y, e0.z, e0.w};
            const float ea1[4] = {e1.x, e1.y, e1.z, e1.w};
            const float ga0[4] = {g0.x, g0.y, g0.z, g0.w};
            const float ga1[4] = {g1.x, g1.y, g1.z, g1.w};
            #pragma unroll
            for (int ii = 0; ii < 4; ii++)
                #pragma unroll
                for (int jj = 0; jj < 4; jj++) {
                    const float r0 = fmaxf(ea0[ii] - ga0[jj], 0.f);
                    const float r1 = fmaxf(ea1[ii] - ga1[jj], 0.f);
                    unsigned long long r2;
                    asm("mov.b64 %0, {%1, %2};" : "=l"(r2) : "f"(r0), "f"(r1));
                    asm("fma.rn.f32x2 %0, %1, %1, %0;" : "+l"(acc2[ii][jj]) : "l"(r2));
                }
        }
    }

    #pragma unroll
    for (int ii = 0; ii < 4; ii++) {
        const int b = b0 + tb + ii;
        #pragma unroll
        for (int jj = 0; jj < 4; jj++) {
            const int n = n0 + tn + jj;
            if (n < N_LABELS) {
                float lo, hi;
                asm("mov.b64 {%0, %1}, %2;" : "=f"(lo), "=f"(hi) : "l"(acc2[ii][jj]));
                out[(size_t)b * N_LABELS + n] = -(lo + hi);
            }
        }
    }
}

// ---------------------------------------------------------------------------
// kernel_launch
// ---------------------------------------------------------------------------
extern "C" void kernel_launch(void* const* d_in, const int* in_sizes, int n_in,
                              void* d_out, int out_size)
{
    const float* vfs = (const float*)d_in[0];
    const float* W1  = (const float*)d_in[1];
    const float* b1  = (const float*)d_in[2];
    const float* W2  = (const float*)d_in[3];
    const float* b2  = (const float*)d_in[4];
    const float* G   = (const float*)d_in[5];

    float* score = (float*)d_out;                            // [512, 2000]
    float* emb   = (float*)d_out + (size_t)M_B * N_LABELS;   // [512, 300]

    __nv_bfloat16 *Ahi, *Alo, *W1hi, *W1lo, *Hhi, *Hlo, *W2hi, *W2lo;
    cudaGetSymbolAddress((void**)&Ahi,  g_Ahi);
    cudaGetSymbolAddress((void**)&Alo,  g_Alo);
    cudaGetSymbolAddress((void**)&W1hi, g_W1hi);
    cudaGetSymbolAddress((void**)&W1lo, g_W1lo);
    cudaGetSymbolAddress((void**)&Hhi,  g_Hhi);
    cudaGetSymbolAddress((void**)&Hlo,  g_Hlo);
    cudaGetSymbolAddress((void**)&W2hi, g_W2hi);
    cudaGetSymbolAddress((void**)&W2lo, g_W2lo);

    cudaFuncSetAttribute(gemm_mma<0>, cudaFuncAttributeMaxDynamicSharedMemorySize, GSMEM);
    cudaFuncSetAttribute(gemm_mma<2>, cudaFuncAttributeMaxDynamicSharedMemorySize, GSMEM);

    // Prep: relu+split vfs; split W1; split+pad W2; seed emb with bias
    relu_split_kernel<<<(M_B * VF_D / 4 + 255) / 256, 256>>>(vfs, Ahi, Alo, M_B * VF_D / 4);
    {
        dim3 g(HID_D / 512, VF_D);
        split_pad_kernel<<<g, 256>>>(W1, W1hi, W1lo, HID_D, HID_D);
    }
    {
        dim3 g(1, HID_D);
        split_pad_kernel<<<g, 256>>>(W2, W2hi, W2lo, EMB_D, EMB_PAD);
    }
    fill_bias_kernel<<<(M_B * (EMB_D / 4) + 255) / 256, 256>>>(
        (float4*)emb, (const float4*)b2);

    // GEMM1: H = relu(vfs) @ W1 + b1 -> relu+split -> Hhi/Hlo  [512, 2048]
    {
        dim3 g(HID_D / GM_BN, M_B / GM_BM, 1);  // (32, 8, 1) = 256 CTAs
        gemm_mma<0><<<g, 256, GSMEM>>>(Ahi, Alo, W1hi, W1lo, b1,
                                       nullptr, Hhi, Hlo, VF_D, HID_D, HID_D, HID_D, VF_D);
    }
    // GEMM2 (split-K x4): emb += relu(H) @ W2  (fp32 atomics; bias pre-seeded)
    {
        dim3 g(EMB_PAD / GM_BN, M_B / GM_BM, 4);  // (5, 8, 4) = 160 CTAs
        gemm_mma<2><<<g, 256, GSMEM>>>(Hhi, Hlo, W2hi, W2lo, nullptr,
                                       emb, nullptr, nullptr, HID_D, EMB_PAD, EMB_D, EMB_D,
                                       HID_D / 4);
    }
    // Score: [512, 2000]
    {
        dim3 g((N_LABELS + 63) / 64, M_B / 64);  // (32, 8)
        order_score<<<g, 256>>>(emb, G, score);
    }
}

// round 11
// speedup vs baseline: 4.1963x; 1.2739x over previous
#include <cuda_runtime.h>
#include <cuda_fp16.h>
#include <cstdint>

// Problem dims (fixed by the reference)
#define M_B      512
#define VF_D     4096
#define HID_D    2048
#define EMB_D    300
#define EMB_PAD  320
#define N_LABELS 2000

// ---------------------------------------------------------------------------
// Scratch (fp16 split operands)
// ---------------------------------------------------------------------------
__device__ __half g_Ahi[M_B * VF_D];        // relu(vfs) fp16 hi
__device__ __half g_Alo[M_B * VF_D];        // relu(vfs) fp16 lo
__device__ __half g_W1h[VF_D * HID_D];      // W1 fp16 (single)
__device__ __half g_Hhi[M_B * HID_D];       // relu(H) fp16 hi
__device__ __half g_Hlo[M_B * HID_D];       // relu(H) fp16 lo
__device__ __half g_W2h[HID_D * EMB_PAD];   // W2 fp16 hi (cols>=300 zero)
__device__ __half g_W2l[HID_D * EMB_PAD];   // W2 fp16 lo

// ---------------------------------------------------------------------------
// Helpers (baseline PTX only: mma.sync / ldmatrix / cp.async / f32x2)
// ---------------------------------------------------------------------------
#define SWZ(off) ((off) ^ (((off) >> 3) & 0x70))

__device__ __forceinline__ uint32_t smem_u32(const void* p) {
    uint32_t a;
    asm("{ .reg .u64 t; cvta.to.shared.u64 t, %1; cvt.u32.u64 %0, t; }" : "=r"(a) : "l"(p));
    return a;
}

__device__ __forceinline__ void cp16(uint32_t smem, const void* g) {
    asm volatile("cp.async.cg.shared.global [%0], [%1], 16;" :: "r"(smem), "l"(g));
}
#define CP_COMMIT() asm volatile("cp.async.commit_group;" ::: "memory")
#define CP_WAIT(n)  asm volatile("cp.async.wait_group %0;" :: "n"(n) : "memory")

__device__ __forceinline__ void ldsm_x4(uint32_t* r, uint32_t addr) {
    asm volatile("ldmatrix.sync.aligned.m8n8.x4.shared.b16 {%0,%1,%2,%3}, [%4];"
        : "=r"(r[0]), "=r"(r[1]), "=r"(r[2]), "=r"(r[3]) : "r"(addr));
}
__device__ __forceinline__ void ldsm_x4_t(uint32_t* r, uint32_t addr) {
    asm volatile("ldmatrix.sync.aligned.m8n8.x4.trans.shared.b16 {%0,%1,%2,%3}, [%4];"
        : "=r"(r[0]), "=r"(r[1]), "=r"(r[2]), "=r"(r[3]) : "r"(addr));
}
__device__ __forceinline__ void mma_f16(float* c, const uint32_t* a, const uint32_t* b) {
    asm volatile("mma.sync.aligned.m16n8k16.row.col.f32.f16.f16.f32 "
        "{%0,%1,%2,%3}, {%4,%5,%6,%7}, {%8,%9}, {%0,%1,%2,%3};"
        : "+f"(c[0]), "+f"(c[1]), "+f"(c[2]), "+f"(c[3])
        : "r"(a[0]), "r"(a[1]), "r"(a[2]), "r"(a[3]), "r"(b[0]), "r"(b[1]));
}

__device__ __forceinline__ void split_h(float r, __half& h, __half& l) {
    h = __float2half_rn(r);
    l = __float2half_rn(r - __half2float(h));
}

// ---------------------------------------------------------------------------
// Merged prep kernel: blockIdx-partitioned jobs
//   [0, 2048)          : relu+split vfs -> Ahi/Alo        (float4 granularity)
//   [2048, 10240)      : W1 fp32 -> fp16 (W1h)            (float4 granularity)
//   [10240, 12288)     : W2 split+pad -> W2h/W2l          (one k-row per block)
//   [12288, 12438)     : emb = bias broadcast             (float4)
// ---------------------------------------------------------------------------
#define PB_VFS   2048
#define PB_W1    8192
#define PB_W2    2048
#define PB_FILL  150
#define PB_TOTAL (PB_VFS + PB_W1 + PB_W2 + PB_FILL)

__global__ __launch_bounds__(256)
void prep_kernel(const float* __restrict__ vfs, const float* __restrict__ W1,
                 const float* __restrict__ W2, const float* __restrict__ b2,
                 __half* __restrict__ Ahi, __half* __restrict__ Alo,
                 __half* __restrict__ W1h,
                 __half* __restrict__ W2h, __half* __restrict__ W2l,
                 float4* __restrict__ emb4)
{
    const int bid = blockIdx.x;
    const int tid = threadIdx.x;

    if (bid < PB_VFS) {
        const int i = bid * 256 + tid;                     // float4 index
        const float4 v = reinterpret_cast<const float4*>(vfs)[i];
        float r[4] = {fmaxf(v.x, 0.f), fmaxf(v.y, 0.f), fmaxf(v.z, 0.f), fmaxf(v.w, 0.f)};
        __half h[4], l[4];
        #pragma unroll
        for (int j = 0; j < 4; j++) split_h(r[j], h[j], l[j]);
        reinterpret_cast<__half2*>(Ahi)[i*2]   = __halves2half2(h[0], h[1]);
        reinterpret_cast<__half2*>(Ahi)[i*2+1] = __halves2half2(h[2], h[3]);
        reinterpret_cast<__half2*>(Alo)[i*2]   = __halves2half2(l[0], l[1]);
        reinterpret_cast<__half2*>(Alo)[i*2+1] = __halves2half2(l[2], l[3]);
    } else if (bid < PB_VFS + PB_W1) {
        const int i = (bid - PB_VFS) * 256 + tid;          // float4 index
        const float4 v = reinterpret_cast<const float4*>(W1)[i];
        reinterpret_cast<__half2*>(W1h)[i*2]   = __halves2half2(__float2half_rn(v.x), __float2half_rn(v.y));
        reinterpret_cast<__half2*>(W1h)[i*2+1] = __halves2half2(__float2half_rn(v.z), __float2half_rn(v.w));
    } else if (bid < PB_VFS + PB_W1 + PB_W2) {
        const int k = bid - (PB_VFS + PB_W1);              // 0..2047
        const int c = tid * 2;
        if (c < EMB_PAD) {
            const float v0 = (c     < EMB_D) ? W2[(size_t)k * EMB_D + c]     : 0.0f;
            const float v1 = (c + 1 < EMB_D) ? W2[(size_t)k * EMB_D + c + 1] : 0.0f;
            __half h0, l0, h1, l1;
            split_h(v0, h0, l0); split_h(v1, h1, l1);
            *reinterpret_cast<__half2*>(W2h + (size_t)k * EMB_PAD + c) = __halves2half2(h0, h1);
            *reinterpret_cast<__half2*>(W2l + (size_t)k * EMB_PAD + c) = __halves2half2(l0, l1);
        }
    } else {
        const int i = (bid - (PB_VFS + PB_W1 + PB_W2)) * 256 + tid;
        if (i < M_B * (EMB_D / 4))
            emb4[i] = reinterpret_cast<const float4*>(b2)[i % (EMB_D / 4)];
    }
}

// ---------------------------------------------------------------------------
// mma.sync GEMM: C[64,64] tile = A[64,K] @ B[K,64]  (fp16, fp32 accum)
// BSPLIT=false: 2 MMAs (Ahi*Bh + Alo*Bh), 4-stage 24KB pipeline   (GEMM1)
// BSPLIT=true : 3 MMAs (+ Ahi*Bl),        3-stage 32KB pipeline   (GEMM2)
// OUT_MODE 0: outHi/outLo = fp16-split(relu(C + bias))   (full K)
// OUT_MODE 2: atomicAdd(outF, C), cols < Nreal            (split-K partial)
// ---------------------------------------------------------------------------
#define GM_BM 64
#define GM_BN 64
#define GM_KC 64
#define GA_B  (GM_BM * 128)            // 8 KB per A matrix

template<int OUT_MODE, bool BSPLIT>
__global__ __launch_bounds__(256, 2)
void gemm_mma(const __half* __restrict__ Ahi, const __half* __restrict__ Alo,
              const __half* __restrict__ Bh, const __half* __restrict__ Bl,
              const float* __restrict__ bias,
              float* __restrict__ outF,
              __half* __restrict__ outHi, __half* __restrict__ outLo,
              int K, int ldB, int Nreal, int ldOut, int kLen)
{
    constexpr int GB_B = GM_BN * 128;                       // 8 KB per B matrix
    constexpr int GSTG = 2 * GA_B + (BSPLIT ? 2 : 1) * GB_B;
    constexpr int NST  = BSPLIT ? 3 : 4;

    extern __shared__ char smem[];
    const uint32_t smem_base = smem_u32(smem);
    const int tid  = threadIdx.x;
    const int lane = tid & 31;
    const int wid  = tid >> 5;
    const int m0 = blockIdx.y * GM_BM;
    const int n0 = blockIdx.x * GM_BN;
    const int kOff = blockIdx.z * kLen;
    const int NC = kLen / GM_KC;

    const int wm0 = (wid >> 2) * 32;
    const int wn0 = (wid & 3) * 16;

    float acc[2][2][4];
    #pragma unroll
    for (int mi = 0; mi < 2; mi++)
        #pragma unroll
        for (int ni = 0; ni < 2; ni++)
            #pragma unroll
            for (int j = 0; j < 4; j++) acc[mi][ni][j] = 0.0f;

    auto load_stage = [&](int s, int k0) {
        const uint32_t base = smem_base + s * GSTG;
        #pragma unroll
        for (int t = 0; t < 2; t++) {
            const int u = tid + t * 256;
            const int row = u >> 3, seg = u & 7;
            const uint32_t off = SWZ((uint32_t)(row * 128 + seg * 16));
            const size_t gi = (size_t)(m0 + row) * K + k0 + seg * 8;
            cp16(base + off,        Ahi + gi);
            cp16(base + GA_B + off, Alo + gi);
        }
        #pragma unroll
        for (int t = 0; t < 2; t++) {
            const int u = tid + t * 256;
            const int row = u >> 3, seg = u & 7;
            const uint32_t off = SWZ((uint32_t)(row * 128 + seg * 16));
            const size_t gi = (size_t)(k0 + row) * ldB + n0 + seg * 8;
            cp16(base + 2*GA_B + off, Bh + gi);
            if (BSPLIT) cp16(base + 2*GA_B + GB_B + off, Bl + gi);
        }
    };

    const uint32_t aoff0 = (uint32_t)((wm0 + (lane & 15)) * 128 + (lane >> 4) * 16);
    const uint32_t boff0 = (uint32_t)((((lane >> 3) & 1) * 8 + (lane & 7)) * 128
                                      + (wn0 + (lane >> 4) * 8) * 2);

    // prologue: NST-1 stages in flight
    #pragma unroll
    for (int s = 0; s < NST - 1; s++) { load_stage(s, kOff + s * GM_KC); CP_COMMIT(); }

    for (int c = 0; c < NC; c++) {
        if      (c <= NC - NST + 1) { CP_WAIT(NST - 2); }
        else if (c == NC - 2)       { CP_WAIT(1); }       // reachable only when NST>=4
        else                        { CP_WAIT(0); }
        __syncthreads();
        if (c + NST - 1 < NC) { load_stage((c + NST - 1) % NST, kOff + (c + NST - 1) * GM_KC); CP_COMMIT(); }

        const uint32_t st = smem_base + (c % NST) * GSTG;
        #pragma unroll
        for (int kk = 0; kk < GM_KC; kk += 16) {
            uint32_t ah[2][4], al[2][4], bh[4], bl[4];
            #pragma unroll
            for (int mi = 0; mi < 2; mi++) {
                const uint32_t off = SWZ(aoff0 + mi * 16 * 128 + kk * 2);
                ldsm_x4(ah[mi], st + off);
                ldsm_x4(al[mi], st + GA_B + off);
            }
            {
                const uint32_t off = SWZ(boff0 + kk * 128);
                ldsm_x4_t(bh, st + 2*GA_B + off);
                if (BSPLIT) ldsm_x4_t(bl, st + 2*GA_B + GB_B + off);
            }
            #pragma unroll
            for (int mi = 0; mi < 2; mi++)
                #pragma unroll
                for (int ni = 0; ni < 2; ni++) {
                    mma_f16(acc[mi][ni], ah[mi], &bh[ni * 2]);              // hi*hi
                    mma_f16(acc[mi][ni], al[mi], &bh[ni * 2]);              // lo*hi
                    if (BSPLIT) mma_f16(acc[mi][ni], ah[mi], &bl[ni * 2]);  // hi*lo
                }
        }
    }

    // --- epilogue ----------------------------------------------------------
    const int g = lane >> 2, t = lane & 3;
    #pragma unroll
    for (int mi = 0; mi < 2; mi++) {
        #pragma unroll
        for (int ni = 0; ni < 2; ni++) {
            const float* cc = acc[mi][ni];
            const int row0 = m0 + wm0 + mi * 16 + g;
            const int col  = n0 + wn0 + ni * 8 + t * 2;
            if (OUT_MODE == 0) {
                const float b0 = bias[col], b1 = bias[col + 1];
                #pragma unroll
                for (int h = 0; h < 2; h++) {
                    const int row = row0 + h * 8;
                    const float r0 = fmaxf(cc[h*2]   + b0, 0.f);
                    const float r1 = fmaxf(cc[h*2+1] + b1, 0.f);
                    __half h0, l0, h1, l1;
                    split_h(r0, h0, l0); split_h(r1, h1, l1);
                    *reinterpret_cast<__half2*>(outHi + (size_t)row * ldOut + col) = __halves2half2(h0, h1);
                    *reinterpret_cast<__half2*>(outLo + (size_t)row * ldOut + col) = __halves2half2(l0, l1);
                }
            } else {
                #pragma unroll
                for (int h = 0; h < 2; h++) {
                    const int row = row0 + h * 8;
                    if (col < Nreal)
                        atomicAdd(outF + (size_t)row * ldOut + col,     cc[h*2]);
                    if (col + 1 < Nreal)
                        atomicAdd(outF + (size_t)row * ldOut + col + 1, cc[h*2+1]);
                }
            }
        }
    }
}

#define GSMEM_G1 (4 * (2 * GA_B + 1 * (GM_BN * 128)))   // 4 stages x 24 KB = 96 KB
#define GSMEM_G2 (3 * (2 * GA_B + 2 * (GM_BN * 128)))   // 3 stages x 32 KB = 96 KB

// ---------------------------------------------------------------------------
// Score: out[b,n] = -sum_d relu(E[b,d] - G[n,d])^2
// 64x64 tile, 4x4 per thread, packed fma.rn.f32x2 accumulation.
// ---------------------------------------------------------------------------
#define SC_DC 60
#define SC_ST 68

__global__ __launch_bounds__(256)
void order_score(const float* __restrict__ E,   // [512, 300]
                 const float* __restrict__ G,   // [2000, 300]
                 float* __restrict__ out)       // [512, 2000]
{
    __shared__ float Es[SC_DC][SC_ST];
    __shared__ float Gs[SC_DC][SC_ST];

    const int tid = threadIdx.x;
    const int n0 = blockIdx.x * 64;
    const int b0 = blockIdx.y * 64;
    const int tb = (tid >> 4) << 2;
    const int tn = (tid & 15) << 2;

    unsigned long long acc2[4][4];
    #pragma unroll
    for (int ii = 0; ii < 4; ii++)
        #pragma unroll
        for (int jj = 0; jj < 4; jj++) acc2[ii][jj] = 0ull;

    for (int d0 = 0; d0 < EMB_D; d0 += SC_DC) {
        __syncthreads();
        for (int i = tid; i < 64 * SC_DC; i += 256) {
            const int d = i / 64, c = i % 64;
            Es[d][c] = E[(size_t)(b0 + c) * EMB_D + d0 + d];
            const int gr = n0 + c;
            Gs[d][c] = (gr < N_LABELS) ? G[(size_t)gr * EMB_D + d0 + d] : 0.0f;
        }
        __syncthreads();
        #pragma unroll 6
        for (int d = 0; d < SC_DC; d += 2) {
            const float4 e0 = *reinterpret_cast<const float4*>(&Es[d][tb]);
            const float4 e1 = *reinterpret_cast<const float4*>(&Es[d+1][tb]);
            const float4 g0 = *reinterpret_cast<const float4*>(&Gs[d][tn]);
            const float4 g1 = *reinterpret_cast<const float4*>(&Gs[d+1][tn]);
            const float ea0[4] = {e0.x, e0.y, e0.z, e0.w};
            const float ea1[4] = {e1.x, e1.y, e1.z, e1.w};
            const float ga0[4] = {g0.x, g0.y, g0.z, g0.w};
            const float ga1[4] = {g1.x, g1.y, g1.z, g1.w};
            #pragma unroll
            for (int ii = 0; ii < 4; ii++)
                #pragma unroll
                for (int jj = 0; jj < 4; jj++) {
                    const float r0 = fmaxf(ea0[ii] - ga0[jj], 0.f);
                    const float r1 = fmaxf(ea1[ii] - ga1[jj], 0.f);
                    unsigned long long r2;
                    asm("mov.b64 %0, {%1, %2};" : "=l"(r2) : "f"(r0), "f"(r1));
                    asm("fma.rn.f32x2 %0, %1, %1, %0;" : "+l"(acc2[ii][jj]) : "l"(r2));
                }
        }
    }

    #pragma unroll
    for (int ii = 0; ii < 4; ii++) {
        const int b = b0 + tb + ii;
        #pragma unroll
        for (int jj = 0; jj < 4; jj++) {
            const int n = n0 + tn + jj;
            if (n < N_LABELS) {
                float lo, hi;
                asm("mov.b64 {%0, %1}, %2;" : "=f"(lo), "=f"(hi) : "l"(acc2[ii][jj]));
                out[(size_t)b * N_LABELS + n] = -(lo + hi);
            }
        }
    }
}

// ---------------------------------------------------------------------------
// kernel_launch
// ---------------------------------------------------------------------------
extern "C" void kernel_launch(void* const* d_in, const int* in_sizes, int n_in,
                              void* d_out, int out_size)
{
    const float* vfs = (const float*)d_in[0];
    const float* W1  = (const float*)d_in[1];
    const float* b1  = (const float*)d_in[2];
    const float* W2  = (const float*)d_in[3];
    const float* b2  = (const float*)d_in[4];
    const float* G   = (const float*)d_in[5];

    float* score = (float*)d_out;                            // [512, 2000]
    float* emb   = (float*)d_out + (size_t)M_B * N_LABELS;   // [512, 300]

    __half *Ahi, *Alo, *W1h, *Hhi, *Hlo, *W2h, *W2l;
    cudaGetSymbolAddress((void**)&Ahi, g_Ahi);
    cudaGetSymbolAddress((void**)&Alo, g_Alo);
    cudaGetSymbolAddress((void**)&W1h, g_W1h);
    cudaGetSymbolAddress((void**)&Hhi, g_Hhi);
    cudaGetSymbolAddress((void**)&Hlo, g_Hlo);
    cudaGetSymbolAddress((void**)&W2h, g_W2h);
    cudaGetSymbolAddress((void**)&W2l, g_W2l);

    cudaFuncSetAttribute(gemm_mma<0,false>, cudaFuncAttributeMaxDynamicSharedMemorySize, GSMEM_G1);
    cudaFuncSetAttribute(gemm_mma<2,true>,  cudaFuncAttributeMaxDynamicSharedMemorySize, GSMEM_G2);

    // Merged prep: relu+split vfs, W1->fp16, W2 split+pad, emb=bias
    prep_kernel<<<PB_TOTAL, 256>>>(vfs, W1, W2, b2, Ahi, Alo, W1h, W2h, W2l, (float4*)emb);

    // GEMM1 (2-term fp16): H = relu(vfs) @ W1 + b1 -> relu+split -> Hhi/Hlo
    {
        dim3 g(HID_D / GM_BN, M_B / GM_BM, 1);  // (32, 8, 1) = 256 CTAs
        gemm_mma<0,false><<<g, 256, GSMEM_G1>>>(Ahi, Alo, W1h, nullptr, b1,
                                                nullptr, Hhi, Hlo, VF_D, HID_D, HID_D, HID_D, VF_D);
    }
    // GEMM2 (3-term fp16, split-K x4): emb += relu(H) @ W2  (bias pre-seeded)
    {
        dim3 g(EMB_PAD / GM_BN, M_B / GM_BM, 4);  // (5, 8, 4) = 160 CTAs
        gemm_mma<2,true><<<g, 256, GSMEM_G2>>>(Hhi, Hlo, W2h, W2l, nullptr,
                                               emb, nullptr, nullptr, HID_D, EMB_PAD, EMB_D, EMB_D,
                                               HID_D / 4);
    }
    // Score: [512, 2000]
    {
        dim3 g((N_LABELS + 63) / 64, M_B / 64);  // (32, 8)
        order_score<<<g, 256>>>(emb, G, score);
    }
}